// round 4
// baseline (speedup 1.0000x reference)
#include <cuda_runtime.h>

#define TT   1024   // sequence length
#define BB   2      // batch
#define HH   128    // hidden
#define NIN  1024   // input dim
#define KC   32     // GEMM K chunk
#define CHUNK 256   // scan time chunk (4 chunks)

#define U_ELEMS   (BB * TT * NIN)   // 2097152
#define LAM_ELEMS (HH)              // 128
#define B_ELEMS   (HH * NIN)        // 131072

// Scratch (no device allocations allowed)
__device__ float2 g_L[HH];             // lambda_bar
__device__ float2 g_w[HH];             // (lambda_bar - 1) / lambda
__device__ float2 g_bu[BB * HH * TT];  // bu[(b*HH + h)*TT + t]

// ---------------------------------------------------------------------------
// Setup: L[h] = exp(lam*delta), w[h] = (L-1)/lam   (complex, fp32)
// ---------------------------------------------------------------------------
__global__ void setup_kernel(const float* delta, float delta_fb,
                             const float* lre, const float* lim) {
    if (lre == nullptr || lim == nullptr) return;
    int h = threadIdx.x;
    float d  = delta ? delta[0] : delta_fb;
    float ar = lre[h], ai = lim[h];
    float er = expf(ar * d);
    float Lr = er * cosf(ai * d);
    float Li = er * sinf(ai * d);
    g_L[h] = make_float2(Lr, Li);
    float nr = Lr - 1.0f, ni = Li;
    float inv = 1.0f / (ar * ar + ai * ai);
    g_w[h] = make_float2((nr * ar + ni * ai) * inv,
                         (ni * ar - nr * ai) * inv);
}

// ---------------------------------------------------------------------------
// GEMM: G[h][t] = sum_i b[h][i] * u[b][t][i]  (re and im), then bu = w[h]*G.
// Block tile: 32 h x 32 t, K chunks of 32. 128 threads, micro 2h x 4t.
// Grid: (32, 4, 2) = 256 blocks.
// ---------------------------------------------------------------------------
__global__ void gemm_kernel(const float* __restrict__ u,
                            const float* __restrict__ bre,
                            const float* __restrict__ bim) {
    if (u == nullptr || bre == nullptr || bim == nullptr) return;

    __shared__ float sBr[32][KC + 1];
    __shared__ float sBi[32][KC + 1];
    __shared__ float sU [32][KC + 1];

    int b   = blockIdx.z;
    int h0  = blockIdx.y * 32;
    int t0  = blockIdx.x * 32;
    int tid = threadIdx.x;            // 0..127
    int hg  = tid >> 3;               // 0..15  -> h_local = hg*2
    int tg  = tid & 7;                // 0..7   -> t_local = tg*4

    float accR[2][4] = {{0.f}}, accI[2][4] = {{0.f}};

    const float* ub = u + ((size_t)b * TT + t0) * NIN;

    for (int k0 = 0; k0 < NIN; k0 += KC) {
        #pragma unroll
        for (int i = 0; i < 8; i++) {
            int idx = i * 128 + tid;
            int r = idx >> 5, c = idx & 31;
            sBr[r][c] = bre[(size_t)(h0 + r) * NIN + k0 + c];
            sBi[r][c] = bim[(size_t)(h0 + r) * NIN + k0 + c];
            sU [r][c] = ub [(size_t)r * NIN + k0 + c];
        }
        __syncthreads();

        #pragma unroll
        for (int k = 0; k < KC; k++) {
            float u0 = sU[tg * 4 + 0][k];
            float u1 = sU[tg * 4 + 1][k];
            float u2 = sU[tg * 4 + 2][k];
            float u3 = sU[tg * 4 + 3][k];
            float br0 = sBr[hg * 2 + 0][k];
            float br1 = sBr[hg * 2 + 1][k];
            float bi0 = sBi[hg * 2 + 0][k];
            float bi1 = sBi[hg * 2 + 1][k];
            accR[0][0] = fmaf(br0, u0, accR[0][0]);
            accR[0][1] = fmaf(br0, u1, accR[0][1]);
            accR[0][2] = fmaf(br0, u2, accR[0][2]);
            accR[0][3] = fmaf(br0, u3, accR[0][3]);
            accR[1][0] = fmaf(br1, u0, accR[1][0]);
            accR[1][1] = fmaf(br1, u1, accR[1][1]);
            accR[1][2] = fmaf(br1, u2, accR[1][2]);
            accR[1][3] = fmaf(br1, u3, accR[1][3]);
            accI[0][0] = fmaf(bi0, u0, accI[0][0]);
            accI[0][1] = fmaf(bi0, u1, accI[0][1]);
            accI[0][2] = fmaf(bi0, u2, accI[0][2]);
            accI[0][3] = fmaf(bi0, u3, accI[0][3]);
            accI[1][0] = fmaf(bi1, u0, accI[1][0]);
            accI[1][1] = fmaf(bi1, u1, accI[1][1]);
            accI[1][2] = fmaf(bi1, u2, accI[1][2]);
            accI[1][3] = fmaf(bi1, u3, accI[1][3]);
        }
        __syncthreads();
    }

    #pragma unroll
    for (int hh = 0; hh < 2; hh++) {
        int h = h0 + hg * 2 + hh;
        float2 w = g_w[h];
        #pragma unroll
        for (int tt = 0; tt < 4; tt++) {
            int t = t0 + tg * 4 + tt;
            float gr = accR[hh][tt], gi = accI[hh][tt];
            g_bu[((size_t)b * HH + h) * TT + t] =
                make_float2(w.x * gr - w.y * gi, w.x * gi + w.y * gr);
        }
    }
}

// ---------------------------------------------------------------------------
// Scan: x[t] = L[h2]*x[t-1] + bu[t,b,h1];  out(t,b,h1,h2) = x[t] (real or cplx)
// Grid (256 = b*h1, 4 time chunks), 128 threads (thread = h2).
// Each block replays the prefix from t=0 (compute-only) then writes its chunk.
// cmode=0: write real part only (float). cmode=1: interleaved re,im (float2).
// All stores bounds-checked against lim_floats.
// ---------------------------------------------------------------------------
__global__ void scan_kernel(float* __restrict__ out, int cmode,
                            size_t lim_floats) {
    __shared__ float2 sbu[TT];

    int bh    = blockIdx.x;       // b*HH + h1
    int chunk = blockIdx.y;       // 0..3
    int h2    = threadIdx.x;      // 0..127

    int t_w0  = chunk * CHUNK;
    int t_end = t_w0 + CHUNK;

    const float2* src = g_bu + (size_t)bh * TT;
    for (int t = h2; t < t_end; t += 128) sbu[t] = src[t];
    __syncthreads();

    float2 L = g_L[h2];
    float xr = 0.f, xi = 0.f;

    // warm-up replay (no writes)
    for (int t = 0; t < t_w0; t++) {
        float2 c = sbu[t];
        float nr = fmaf(L.x, xr, fmaf(-L.y, xi, c.x));
        float ni = fmaf(L.x, xi, fmaf( L.y, xr, c.y));
        xr = nr; xi = ni;
    }

    int b = bh >> 7, h1 = bh & 127;
    size_t off = ((size_t)(t_w0 * BB + b) * HH + h1) * HH + h2;  // complex idx
    const size_t stride = (size_t)BB * HH * HH;

    if (cmode) {
        for (int t = t_w0; t < t_end; t++) {
            float2 c = sbu[t];
            float nr = fmaf(L.x, xr, fmaf(-L.y, xi, c.x));
            float ni = fmaf(L.x, xi, fmaf( L.y, xr, c.y));
            xr = nr; xi = ni;
            size_t f = off * 2;
            if (f + 1 < lim_floats)
                reinterpret_cast<float2*>(out)[off] = make_float2(xr, xi);
            off += stride;
        }
    } else {
        for (int t = t_w0; t < t_end; t++) {
            float2 c = sbu[t];
            float nr = fmaf(L.x, xr, fmaf(-L.y, xi, c.x));
            float ni = fmaf(L.x, xi, fmaf( L.y, xr, c.y));
            xr = nr; xi = ni;
            if (off < lim_floats) out[off] = xr;
            off += stride;
        }
    }
}

// ---------------------------------------------------------------------------
// Host: robust binding + crash-proof output-mode selection.
// ---------------------------------------------------------------------------
extern "C" void kernel_launch(void* const* d_in, const int* in_sizes, int n_in,
                              void* d_out, int out_size) {
    // --- detect element-count vs byte-count in_sizes ---
    int div = 0;
    for (int i = 0; i < n_in && !div; i++) {
        if (in_sizes[i] == U_ELEMS)     div = 1;
        if (in_sizes[i] == U_ELEMS * 4) div = 4;
    }
    if (!div) div = 1;

    const float* u = nullptr;
    const float* delta = nullptr;
    const float* lam[2]  = {nullptr, nullptr};
    const float* bmat[2] = {nullptr, nullptr};
    int nl = 0, nb = 0, u_idx = -1;

    for (int i = 0; i < n_in; i++) {
        long long s = (long long)in_sizes[i] / div;
        const float* p = (const float*)d_in[i];
        if (s == U_ELEMS)        { u = p; u_idx = i; }
        else if (s == 1)           delta = p;
        else if (s == LAM_ELEMS) { if (nl < 2) lam[nl++] = p; }
        else if (s == B_ELEMS)   { if (nb < 2) bmat[nb++] = p; }
    }

    if ((!u || nl < 2 || nb < 2) && n_in >= 6) {   // positional fallback
        u       = (const float*)d_in[0];
        delta   = (const float*)d_in[1];
        lam[0]  = (const float*)d_in[2];
        lam[1]  = (const float*)d_in[3];
        bmat[0] = (const float*)d_in[4];
        bmat[1] = (const float*)d_in[5];
        u_idx = 0; nl = nb = 2;
    }

    // dict order (u first) -> re precedes im; alphabetical (u last) -> im first
    bool re_first = (u_idx == 0);
    const float* lre = re_first ? lam[0]  : lam[1];
    const float* lim = re_first ? lam[1]  : lam[0];
    const float* bre = re_first ? bmat[0] : bmat[1];
    const float* bim = re_first ? bmat[1] : bmat[0];

    // --- output mode decision table (crash-proof for every interpretation) ---
    const long long full_c = (long long)TT * BB * HH * HH;   // 33,554,432 complex
    int cmode;              // 0 = real floats, 1 = interleaved complex floats
    size_t lim_floats;
    long long os = out_size;
    if (os == full_c) {                 // float32 real count (likely; also safe
        cmode = 0; lim_floats = (size_t)full_c;  // if buffer is complex64)
    } else if (os == 2 * full_c) {      // float count, interleaved complex
        cmode = 1; lim_floats = (size_t)(2 * full_c);
    } else if (os == 8 * full_c) {      // byte count, complex64
        cmode = 1; lim_floats = (size_t)(2 * full_c);
    } else if (os == 4 * full_c) {      // byte count, float32 real
        cmode = 0; lim_floats = (size_t)full_c;
    } else {                            // unknown: clamped real mode
        cmode = 0;
        lim_floats = (size_t)(os < full_c ? (os > 0 ? os : 0) : full_c);
    }

    setup_kernel<<<1, 128>>>(delta, 0.01f, lre, lim);
    gemm_kernel<<<dim3(TT / 32, HH / 32, BB), 128>>>(u, bre, bim);
    scan_kernel<<<dim3(BB * HH, TT / CHUNK), 128>>>((float*)d_out, cmode,
                                                    lim_floats);
}

// round 5
// speedup vs baseline: 1.0067x; 1.0067x over previous
#include <cuda_runtime.h>
#include <cstdint>

#define TT   1024   // sequence length
#define BB   2      // batch
#define HH   128    // hidden
#define NIN  1024   // input dim
#define KC   64     // GEMM K chunk
#define CHUNK 256   // scan time chunk (4 chunks)

#define U_ELEMS   (BB * TT * NIN)   // 2097152
#define LAM_ELEMS (HH)              // 128
#define B_ELEMS   (HH * NIN)        // 131072

// Scratch (no device allocations allowed)
__device__ float2 g_bu[BB * HH * TT];  // bu[(b*HH + h)*TT + t]

// Packed fp32x2 FMA: d = a*b + c, lanewise on (lo,hi). sm_103a FFMA2.
__device__ __forceinline__ unsigned long long
fma2(unsigned long long a, unsigned long long b, unsigned long long c) {
    unsigned long long d;
    asm("fma.rn.f32x2 %0, %1, %2, %3;" : "=l"(d) : "l"(a), "l"(b), "l"(c));
    return d;
}
__device__ __forceinline__ unsigned long long pack2(float lo, float hi) {
    unsigned long long d;
    asm("mov.b64 %0, {%1, %2};" : "=l"(d)
        : "r"(__float_as_uint(lo)), "r"(__float_as_uint(hi)));
    return d;
}
__device__ __forceinline__ void unpack2(unsigned long long v, float& lo, float& hi) {
    unsigned int a, b;
    asm("mov.b64 {%0, %1}, %2;" : "=r"(a), "=r"(b) : "l"(v));
    lo = __uint_as_float(a); hi = __uint_as_float(b);
}

// ---------------------------------------------------------------------------
// GEMM: G[h][t] = sum_i b[h][i]*u[b][t][i] (re,im packed), bu = w[h]*G.
// Block tile 32h x 32t, K chunks of 64, 128 threads.
// Micro: 4h x 2t per thread (hg = tid>>4 -> 8 groups of 4h; tg = tid&15 -> 16
// groups of 2t). Accumulators are packed (re,im) pairs -> 8 FFMA2 per k.
// sB[k][h] float2 (br,bi) interleaved, LDS.128 reads 2 h-pairs.
// sU[t][k] scalar floats, conflict-free.
// Epilogue computes w[h] = (exp(lam*delta)-1)/lam inline (setup kernel folded).
// Grid: (32, 4, 2) = 256 blocks.
// ---------------------------------------------------------------------------
__global__ void gemm_kernel(const float* __restrict__ u,
                            const float* __restrict__ bre,
                            const float* __restrict__ bim,
                            const float* __restrict__ lre,
                            const float* __restrict__ lim,
                            const float* __restrict__ delta) {
    if (u == nullptr || bre == nullptr || bim == nullptr) return;

    __shared__ __align__(16) float2 sB[KC][34];   // [k][h], pad
    __shared__ float sU[32][KC + 1];              // [t][k], pad

    int b   = blockIdx.z;
    int h0  = blockIdx.y * 32;
    int t0  = blockIdx.x * 32;
    int tid = threadIdx.x;            // 0..127
    int hg  = tid >> 4;               // 0..7  -> h_local = hg*4
    int tg  = tid & 15;               // 0..15 -> t_local = tg*2

    unsigned long long acc[4][2];
    #pragma unroll
    for (int i = 0; i < 4; i++)
        #pragma unroll
        for (int j = 0; j < 2; j++) acc[i][j] = 0ull;

    const float* ub = u + ((size_t)b * TT + t0) * NIN;

    for (int k0 = 0; k0 < NIN; k0 += KC) {
        // --- load B: 64k x 32h interleaved (16 float2 per thread) ---
        #pragma unroll
        for (int i = 0; i < 16; i++) {
            int idx = i * 128 + tid;
            int r = idx >> 6;          // h 0..31
            int c = idx & 63;          // k 0..63
            sB[c][r] = make_float2(bre[(size_t)(h0 + r) * NIN + k0 + c],
                                   bim[(size_t)(h0 + r) * NIN + k0 + c]);
        }
        // --- load U: 32t x 64k scalar (16 floats per thread) ---
        #pragma unroll
        for (int i = 0; i < 16; i++) {
            int idx = i * 128 + tid;
            int r = idx >> 6;          // t 0..31
            int c = idx & 63;          // k 0..63
            sU[r][c] = ub[(size_t)r * NIN + k0 + c];
        }
        __syncthreads();

        #pragma unroll 8
        for (int k = 0; k < KC; k++) {
            // 4 h pairs via two LDS.128
            ulonglong2 B01 = *reinterpret_cast<const ulonglong2*>(&sB[k][hg * 4]);
            ulonglong2 B23 = *reinterpret_cast<const ulonglong2*>(&sB[k][hg * 4 + 2]);
            float uv0 = sU[tg * 2 + 0][k];
            float uv1 = sU[tg * 2 + 1][k];
            unsigned long long up0 = pack2(uv0, uv0);
            unsigned long long up1 = pack2(uv1, uv1);
            acc[0][0] = fma2(B01.x, up0, acc[0][0]);
            acc[0][1] = fma2(B01.x, up1, acc[0][1]);
            acc[1][0] = fma2(B01.y, up0, acc[1][0]);
            acc[1][1] = fma2(B01.y, up1, acc[1][1]);
            acc[2][0] = fma2(B23.x, up0, acc[2][0]);
            acc[2][1] = fma2(B23.x, up1, acc[2][1]);
            acc[3][0] = fma2(B23.y, up0, acc[3][0]);
            acc[3][1] = fma2(B23.y, up1, acc[3][1]);
        }
        __syncthreads();
    }

    // Epilogue: w[h] computed inline, bu = w * (Gre + i Gim)
    float d = delta ? delta[0] : 0.01f;
    #pragma unroll
    for (int hh = 0; hh < 4; hh++) {
        int h = h0 + hg * 4 + hh;
        float ar = lre[h], ai = lim[h];
        float er = expf(ar * d);
        float Lr = er * cosf(ai * d);
        float Li = er * sinf(ai * d);
        float nr = Lr - 1.0f, ni = Li;
        float inv = 1.0f / (ar * ar + ai * ai);
        float wr = (nr * ar + ni * ai) * inv;
        float wi = (ni * ar - nr * ai) * inv;
        #pragma unroll
        for (int tt = 0; tt < 2; tt++) {
            int t = t0 + tg * 2 + tt;
            float gr, gi;
            unpack2(acc[hh][tt], gr, gi);
            g_bu[((size_t)b * HH + h) * TT + t] =
                make_float2(wr * gr - wi * gi, wr * gi + wi * gr);
        }
    }
}

// ---------------------------------------------------------------------------
// Scan: x[t] = L[h2]*x[t-1] + bu[t,b,h1]; out(t,b,h1,h2) = Re(x[t]) (cmode=0)
// or interleaved (re,im) (cmode=1). L computed inline per thread.
// Grid (256 = b*h1, 4 time chunks), 128 threads (thread = h2).
// Prefix replayed from t=0 (compute only), then chunk written.
// ---------------------------------------------------------------------------
__global__ void scan_kernel(float* __restrict__ out,
                            const float* __restrict__ lre,
                            const float* __restrict__ lim,
                            const float* __restrict__ delta,
                            int cmode, size_t lim_floats) {
    __shared__ float2 sbu[TT];

    int bh    = blockIdx.x;       // b*HH + h1
    int chunk = blockIdx.y;       // 0..3
    int h2    = threadIdx.x;      // 0..127

    int t_w0  = chunk * CHUNK;
    int t_end = t_w0 + CHUNK;

    const float2* src = g_bu + (size_t)bh * TT;
    for (int t = h2; t < t_end; t += 128) sbu[t] = src[t];
    __syncthreads();

    float d  = delta ? delta[0] : 0.01f;
    float ar = lre[h2], ai = lim[h2];
    float er = expf(ar * d);
    float Lx = er * cosf(ai * d);
    float Ly = er * sinf(ai * d);

    float xr = 0.f, xi = 0.f;

    for (int t = 0; t < t_w0; t++) {      // warm-up replay (no writes)
        float2 c = sbu[t];
        float nr = fmaf(Lx, xr, fmaf(-Ly, xi, c.x));
        float ni = fmaf(Lx, xi, fmaf( Ly, xr, c.y));
        xr = nr; xi = ni;
    }

    int b = bh >> 7, h1 = bh & 127;
    size_t off = ((size_t)(t_w0 * BB + b) * HH + h1) * HH + h2;  // complex idx
    const size_t stride = (size_t)BB * HH * HH;

    if (cmode) {
        for (int t = t_w0; t < t_end; t++) {
            float2 c = sbu[t];
            float nr = fmaf(Lx, xr, fmaf(-Ly, xi, c.x));
            float ni = fmaf(Lx, xi, fmaf( Ly, xr, c.y));
            xr = nr; xi = ni;
            if (off * 2 + 1 < lim_floats)
                reinterpret_cast<float2*>(out)[off] = make_float2(xr, xi);
            off += stride;
        }
    } else {
        for (int t = t_w0; t < t_end; t++) {
            float2 c = sbu[t];
            float nr = fmaf(Lx, xr, fmaf(-Ly, xi, c.x));
            float ni = fmaf(Lx, xi, fmaf( Ly, xr, c.y));
            xr = nr; xi = ni;
            if (off < lim_floats) out[off] = xr;
            off += stride;
        }
    }
}

// ---------------------------------------------------------------------------
// Host: robust binding (proven in R4) + output-mode decision table.
// ---------------------------------------------------------------------------
extern "C" void kernel_launch(void* const* d_in, const int* in_sizes, int n_in,
                              void* d_out, int out_size) {
    int div = 0;
    for (int i = 0; i < n_in && !div; i++) {
        if (in_sizes[i] == U_ELEMS)     div = 1;
        if (in_sizes[i] == U_ELEMS * 4) div = 4;
    }
    if (!div) div = 1;

    const float* u = nullptr;
    const float* delta = nullptr;
    const float* lam[2]  = {nullptr, nullptr};
    const float* bmat[2] = {nullptr, nullptr};
    int nl = 0, nb = 0, u_idx = -1;

    for (int i = 0; i < n_in; i++) {
        long long s = (long long)in_sizes[i] / div;
        const float* p = (const float*)d_in[i];
        if (s == U_ELEMS)        { u = p; u_idx = i; }
        else if (s == 1)           delta = p;
        else if (s == LAM_ELEMS) { if (nl < 2) lam[nl++] = p; }
        else if (s == B_ELEMS)   { if (nb < 2) bmat[nb++] = p; }
    }

    if ((!u || nl < 2 || nb < 2) && n_in >= 6) {   // positional fallback
        u       = (const float*)d_in[0];
        delta   = (const float*)d_in[1];
        lam[0]  = (const float*)d_in[2];
        lam[1]  = (const float*)d_in[3];
        bmat[0] = (const float*)d_in[4];
        bmat[1] = (const float*)d_in[5];
        u_idx = 0; nl = nb = 2;
    }

    bool re_first = (u_idx == 0);
    const float* lre = re_first ? lam[0]  : lam[1];
    const float* lim = re_first ? lam[1]  : lam[0];
    const float* bre = re_first ? bmat[0] : bmat[1];
    const float* bim = re_first ? bmat[1] : bmat[0];

    const long long full_c = (long long)TT * BB * HH * HH;   // 33,554,432
    int cmode; size_t lim_floats;
    long long os = out_size;
    if (os == full_c)          { cmode = 0; lim_floats = (size_t)full_c; }
    else if (os == 2 * full_c) { cmode = 1; lim_floats = (size_t)(2 * full_c); }
    else if (os == 8 * full_c) { cmode = 1; lim_floats = (size_t)(2 * full_c); }
    else if (os == 4 * full_c) { cmode = 0; lim_floats = (size_t)full_c; }
    else { cmode = 0;
           lim_floats = (size_t)(os < full_c ? (os > 0 ? os : 0) : full_c); }

    gemm_kernel<<<dim3(TT / 32, HH / 32, BB), 128>>>(u, bre, bim, lre, lim, delta);
    scan_kernel<<<dim3(BB * HH, TT / CHUNK), 128>>>((float*)d_out, lre, lim,
                                                    delta, cmode, lim_floats);
}

// round 6
// speedup vs baseline: 1.2526x; 1.2443x over previous
#include <cuda_runtime.h>
#include <cstdint>

#define TT   1024   // sequence length
#define BB   2      // batch
#define HH   128    // hidden
#define NIN  1024   // input dim
#define MM   (BB * TT)  // 2048 flattened (b,t) rows
#define KC   32     // GEMM K chunk (double-buffered)
#define NKC  (NIN / KC)          // 32 chunks
#define CH_T 128    // scan chunk length
#define NCH  (TT / CH_T)         // 8 chunks

#define U_ELEMS   (BB * TT * NIN)   // 2097152
#define LAM_ELEMS (HH)              // 128
#define B_ELEMS   (HH * NIN)        // 131072

// Scratch (no device allocations allowed)
__device__ float2 g_wv[HH];                      // w[h] = (exp(lam d)-1)/lam
__device__ float2 g_Bw[NIN * HH];                // Bw[k][h] = w[h]*(bre+i bim)
__device__ float2 g_bu[MM * HH];                 // bu[(b*HH+h)*TT + t]
__device__ float2 g_carry[BB * HH][NCH - 1][HH]; // chunk-boundary states

// ---- packed fp32x2 helpers (sm_103a FFMA2 via PTX) ------------------------
__device__ __forceinline__ unsigned long long
fma2(unsigned long long a, unsigned long long b, unsigned long long c) {
    unsigned long long d;
    asm("fma.rn.f32x2 %0, %1, %2, %3;" : "=l"(d) : "l"(a), "l"(b), "l"(c));
    return d;
}
__device__ __forceinline__ unsigned long long pack2(float lo, float hi) {
    unsigned long long d;
    asm("mov.b64 %0, {%1, %2};" : "=l"(d)
        : "r"(__float_as_uint(lo)), "r"(__float_as_uint(hi)));
    return d;
}
__device__ __forceinline__ void unpack2(unsigned long long v, float& lo, float& hi) {
    unsigned int a, b;
    asm("mov.b64 {%0, %1}, %2;" : "=r"(a), "=r"(b) : "l"(v));
    lo = __uint_as_float(a); hi = __uint_as_float(b);
}

// ---- cp.async helpers -----------------------------------------------------
__device__ __forceinline__ uint32_t smem_u32(const void* p) {
    uint32_t a;
    asm("{ .reg .u64 t; cvta.to.shared.u64 t, %1; cvt.u32.u64 %0, t; }"
        : "=r"(a) : "l"(p));
    return a;
}
__device__ __forceinline__ void cp16(uint32_t dst, const void* src) {
    asm volatile("cp.async.cg.shared.global [%0], [%1], 16;"
                 :: "r"(dst), "l"(src));
}
__device__ __forceinline__ void cp4(uint32_t dst, const void* src) {
    asm volatile("cp.async.ca.shared.global [%0], [%1], 4;"
                 :: "r"(dst), "l"(src));
}
__device__ __forceinline__ void cp_commit() {
    asm volatile("cp.async.commit_group;");
}
template <int N>
__device__ __forceinline__ void cp_wait() {
    asm volatile("cp.async.wait_group %0;" :: "n"(N));
}

// ---------------------------------------------------------------------------
// prep1: g_wv[h] = (exp(lam*delta) - 1) / lam
// ---------------------------------------------------------------------------
__global__ void prep1_kernel(const float* delta, const float* lre,
                             const float* lim) {
    if (!lre || !lim) return;
    int h = threadIdx.x;
    float d  = delta ? delta[0] : 0.01f;
    float ar = lre[h], ai = lim[h];
    float er = expf(ar * d);
    float Lr = er * cosf(ai * d);
    float Li = er * sinf(ai * d);
    float nr = Lr - 1.0f, ni = Li;
    float inv = 1.0f / (ar * ar + ai * ai);
    g_wv[h] = make_float2((nr * ar + ni * ai) * inv,
                          (ni * ar - nr * ai) * inv);
}

// ---------------------------------------------------------------------------
// prep2: g_Bw[k][h] = w[h] * (bre[h][k] + i*bim[h][k])   (transpose+scale)
// ---------------------------------------------------------------------------
__global__ void prep2_kernel(const float* __restrict__ bre,
                             const float* __restrict__ bim) {
    if (!bre || !bim) return;
    int idx = blockIdx.x * 256 + threadIdx.x;   // 0 .. 131071
    int k = idx >> 7, h = idx & 127;
    float2 w = g_wv[h];
    float br = bre[(size_t)h * NIN + k];
    float bi = bim[(size_t)h * NIN + k];
    g_Bw[idx] = make_float2(w.x * br - w.y * bi, w.x * bi + w.y * br);
}

// ---------------------------------------------------------------------------
// GEMM: bu[h][m] = sum_k Bw[k][h] * u[m][k]   (complex x real)
// Block 32h x 32m, 128 threads, micro 4h x 2m, packed (re,im) accumulators.
// Double-buffered cp.async: smem load of chunk c+1 overlaps compute of c.
// Grid: (MM/32 = 64, HH/32 = 4).
// ---------------------------------------------------------------------------
__global__ void gemm_kernel(const float* __restrict__ u) {
    if (!u) return;

    __shared__ __align__(16) float2 sB[2][KC][32];      // [buf][k][h] 16 KB
    __shared__ float sU[2][32][KC + 1];                 // [buf][m][k] 8.25 KB

    int h0  = blockIdx.y * 32;
    int m0  = blockIdx.x * 32;
    int tid = threadIdx.x;            // 0..127
    int hg  = tid >> 4;               // 0..7  -> h_local = hg*4
    int tg  = tid & 15;               // 0..15 -> m_local = tg*2

    // cp.async source/dst precompute
    // B: 512 x 16B segs per chunk -> 4 per thread. seg idx = i*128+tid:
    //    k = idx>>4, s = idx&15  (s = pair-of-float2 within 32 h)
    // U: 1024 x 4B per chunk -> 8 per thread. idx: r = idx>>5 (m), c = idx&31
    uint32_t sB_base = smem_u32(&sB[0][0][0]);
    uint32_t sU_base = smem_u32(&sU[0][0][0]);

    auto issue_chunk = [&](int c, int buf) {
        const float2* gb = g_Bw + (size_t)(c * KC) * HH + h0;
        #pragma unroll
        for (int i = 0; i < 4; i++) {
            int idx = i * 128 + tid;
            int k = idx >> 4, s = idx & 15;
            cp16(sB_base + (uint32_t)(buf * KC * 32 + k * 32 + s * 2) * 8,
                 gb + (size_t)k * HH + s * 2);
        }
        const float* gu = u + (size_t)m0 * NIN + c * KC;
        #pragma unroll
        for (int i = 0; i < 8; i++) {
            int idx = i * 128 + tid;
            int r = idx >> 5, cc = idx & 31;
            cp4(sU_base + (uint32_t)(buf * 32 * (KC + 1) + r * (KC + 1) + cc) * 4,
                gu + (size_t)r * NIN + cc);
        }
        cp_commit();
    };

    unsigned long long acc[4][2];
    #pragma unroll
    for (int i = 0; i < 4; i++) { acc[i][0] = 0ull; acc[i][1] = 0ull; }

    issue_chunk(0, 0);

    for (int c = 0; c < NKC; c++) {
        int buf = c & 1;
        if (c + 1 < NKC) { issue_chunk(c + 1, buf ^ 1); cp_wait<1>(); }
        else             { cp_wait<0>(); }
        __syncthreads();

        #pragma unroll 8
        for (int k = 0; k < KC; k++) {
            ulonglong2 B01 = *reinterpret_cast<const ulonglong2*>(&sB[buf][k][hg * 4]);
            ulonglong2 B23 = *reinterpret_cast<const ulonglong2*>(&sB[buf][k][hg * 4 + 2]);
            float u0 = sU[buf][tg * 2 + 0][k];
            float u1 = sU[buf][tg * 2 + 1][k];
            unsigned long long up0 = pack2(u0, u0);
            unsigned long long up1 = pack2(u1, u1);
            acc[0][0] = fma2(B01.x, up0, acc[0][0]);
            acc[0][1] = fma2(B01.x, up1, acc[0][1]);
            acc[1][0] = fma2(B01.y, up0, acc[1][0]);
            acc[1][1] = fma2(B01.y, up1, acc[1][1]);
            acc[2][0] = fma2(B23.x, up0, acc[2][0]);
            acc[2][1] = fma2(B23.x, up1, acc[2][1]);
            acc[3][0] = fma2(B23.y, up0, acc[3][0]);
            acc[3][1] = fma2(B23.y, up1, acc[3][1]);
        }
        __syncthreads();
    }

    // Epilogue: plain store (w already folded into Bw)
    #pragma unroll
    for (int hh = 0; hh < 4; hh++) {
        int h = h0 + hg * 4 + hh;
        #pragma unroll
        for (int tt = 0; tt < 2; tt++) {
            int m = m0 + tg * 2 + tt;
            int b = m >> 10, t = m & 1023;
            float gr, gi;
            unpack2(acc[hh][tt], gr, gi);
            g_bu[((size_t)b * HH + h) * TT + t] = make_float2(gr, gi);
        }
    }
}

// ---------------------------------------------------------------------------
// Carry kernel: one block per (b,h1); scan all T, store state at each chunk
// boundary (t = 127, 255, ..., 895) into g_carry. Grid 256, 128 threads (h2).
// ---------------------------------------------------------------------------
__global__ void carry_kernel(const float* __restrict__ lre,
                             const float* __restrict__ lim,
                             const float* __restrict__ delta) {
    __shared__ float2 sbu[TT];
    int bh = blockIdx.x;
    int h2 = threadIdx.x;

    const float2* src = g_bu + (size_t)bh * TT;
    #pragma unroll
    for (int i = 0; i < TT / 128; i++) sbu[i * 128 + h2] = src[i * 128 + h2];
    __syncthreads();

    float d  = delta ? delta[0] : 0.01f;
    float ar = lre[h2], ai = lim[h2];
    float er = expf(ar * d);
    float Lx = er * cosf(ai * d);
    float Ly = er * sinf(ai * d);

    float xr = 0.f, xi = 0.f;
    for (int ch = 0; ch < NCH - 1; ch++) {
        #pragma unroll 4
        for (int t = ch * CH_T; t < (ch + 1) * CH_T; t++) {
            float2 c = sbu[t];
            float nr = fmaf(Lx, xr, fmaf(-Ly, xi, c.x));
            float ni = fmaf(Lx, xi, fmaf( Ly, xr, c.y));
            xr = nr; xi = ni;
        }
        g_carry[bh][ch][h2] = make_float2(xr, xi);
    }
}

// ---------------------------------------------------------------------------
// Chunk kernel: grid (256 bh, 8 chunks), 128 threads (h2). No warm-up: init
// from g_carry. Writes real part (cmode=0) or interleaved complex (cmode=1).
// ---------------------------------------------------------------------------
__global__ void chunk_kernel(float* __restrict__ out,
                             const float* __restrict__ lre,
                             const float* __restrict__ lim,
                             const float* __restrict__ delta,
                             int cmode, size_t lim_floats) {
    __shared__ float2 sbu[CH_T];

    int bh    = blockIdx.x;
    int chunk = blockIdx.y;
    int h2    = threadIdx.x;
    int t0    = chunk * CH_T;

    sbu[h2] = g_bu[(size_t)bh * TT + t0 + h2];
    __syncthreads();

    float d  = delta ? delta[0] : 0.01f;
    float ar = lre[h2], ai = lim[h2];
    float er = expf(ar * d);
    float Lx = er * cosf(ai * d);
    float Ly = er * sinf(ai * d);

    float xr = 0.f, xi = 0.f;
    if (chunk > 0) {
        float2 cs = g_carry[bh][chunk - 1][h2];
        xr = cs.x; xi = cs.y;
    }

    int b = bh >> 7, h1 = bh & 127;
    size_t off = ((size_t)(t0 * BB + b) * HH + h1) * HH + h2;  // complex index
    const size_t stride = (size_t)BB * HH * HH;

    if (cmode) {
        #pragma unroll 4
        for (int t = 0; t < CH_T; t++) {
            float2 c = sbu[t];
            float nr = fmaf(Lx, xr, fmaf(-Ly, xi, c.x));
            float ni = fmaf(Lx, xi, fmaf( Ly, xr, c.y));
            xr = nr; xi = ni;
            if (off * 2 + 1 < lim_floats)
                reinterpret_cast<float2*>(out)[off] = make_float2(xr, xi);
            off += stride;
        }
    } else {
        #pragma unroll 4
        for (int t = 0; t < CH_T; t++) {
            float2 c = sbu[t];
            float nr = fmaf(Lx, xr, fmaf(-Ly, xi, c.x));
            float ni = fmaf(Lx, xi, fmaf( Ly, xr, c.y));
            xr = nr; xi = ni;
            if (off < lim_floats) out[off] = xr;
            off += stride;
        }
    }
}

// ---------------------------------------------------------------------------
// Host: robust binding (proven in R4) + output-mode decision table.
// ---------------------------------------------------------------------------
extern "C" void kernel_launch(void* const* d_in, const int* in_sizes, int n_in,
                              void* d_out, int out_size) {
    int div = 0;
    for (int i = 0; i < n_in && !div; i++) {
        if (in_sizes[i] == U_ELEMS)     div = 1;
        if (in_sizes[i] == U_ELEMS * 4) div = 4;
    }
    if (!div) div = 1;

    const float* u = nullptr;
    const float* delta = nullptr;
    const float* lam[2]  = {nullptr, nullptr};
    const float* bmat[2] = {nullptr, nullptr};
    int nl = 0, nb = 0, u_idx = -1;

    for (int i = 0; i < n_in; i++) {
        long long s = (long long)in_sizes[i] / div;
        const float* p = (const float*)d_in[i];
        if (s == U_ELEMS)        { u = p; u_idx = i; }
        else if (s == 1)           delta = p;
        else if (s == LAM_ELEMS) { if (nl < 2) lam[nl++] = p; }
        else if (s == B_ELEMS)   { if (nb < 2) bmat[nb++] = p; }
    }

    if ((!u || nl < 2 || nb < 2) && n_in >= 6) {   // positional fallback
        u       = (const float*)d_in[0];
        delta   = (const float*)d_in[1];
        lam[0]  = (const float*)d_in[2];
        lam[1]  = (const float*)d_in[3];
        bmat[0] = (const float*)d_in[4];
        bmat[1] = (const float*)d_in[5];
        u_idx = 0; nl = nb = 2;
    }

    bool re_first = (u_idx == 0);
    const float* lre = re_first ? lam[0]  : lam[1];
    const float* lim = re_first ? lam[1]  : lam[0];
    const float* bre = re_first ? bmat[0] : bmat[1];
    const float* bim = re_first ? bmat[1] : bmat[0];

    const long long full_c = (long long)TT * BB * HH * HH;   // 33,554,432
    int cmode; size_t lim_floats;
    long long os = out_size;
    if (os == full_c)          { cmode = 0; lim_floats = (size_t)full_c; }
    else if (os == 2 * full_c) { cmode = 1; lim_floats = (size_t)(2 * full_c); }
    else if (os == 8 * full_c) { cmode = 1; lim_floats = (size_t)(2 * full_c); }
    else if (os == 4 * full_c) { cmode = 0; lim_floats = (size_t)full_c; }
    else { cmode = 0;
           lim_floats = (size_t)(os < full_c ? (os > 0 ? os : 0) : full_c); }

    prep1_kernel<<<1, 128>>>(delta, lre, lim);
    prep2_kernel<<<B_ELEMS / 256, 256>>>(bre, bim);
    gemm_kernel<<<dim3(MM / 32, HH / 32), 128>>>(u);
    carry_kernel<<<BB * HH, 128>>>(lre, lim, delta);
    chunk_kernel<<<dim3(BB * HH, NCH), 128>>>((float*)d_out, lre, lim, delta,
                                              cmode, lim_floats);
}

// round 7
// speedup vs baseline: 1.2868x; 1.0273x over previous
#include <cuda_runtime.h>
#include <cstdint>

#define TT   1024   // sequence length
#define BB   2      // batch
#define HH   128    // hidden
#define NIN  1024   // input dim
#define MM   (BB * TT)  // 2048 flattened (b,t) rows
#define KC   32     // GEMM K chunk (double-buffered)
#define NKC  (NIN / KC)          // 32 chunks
#define CH_T 128    // scan chunk length
#define NCH  (TT / CH_T)         // 8 chunks

#define U_ELEMS   (BB * TT * NIN)   // 2097152
#define LAM_ELEMS (HH)              // 128
#define B_ELEMS   (HH * NIN)        // 131072

// Scratch (no device allocations allowed)
__device__ __align__(16) float2 g_Bw[NIN * HH];  // Bw[k][h] = w[h]*(bre+i bim)
__device__ float2 g_bu[MM * HH];                 // bu[(b*HH+h)*TT + t]
__device__ float2 g_carry[BB * HH][NCH - 1][HH]; // partials, then carries

// ---- packed fp32x2 helpers (sm_103a FFMA2 via PTX) ------------------------
__device__ __forceinline__ unsigned long long
fma2(unsigned long long a, unsigned long long b, unsigned long long c) {
    unsigned long long d;
    asm("fma.rn.f32x2 %0, %1, %2, %3;" : "=l"(d) : "l"(a), "l"(b), "l"(c));
    return d;
}
__device__ __forceinline__ unsigned long long pack2(float lo, float hi) {
    unsigned long long d;
    asm("mov.b64 %0, {%1, %2};" : "=l"(d)
        : "r"(__float_as_uint(lo)), "r"(__float_as_uint(hi)));
    return d;
}
__device__ __forceinline__ void unpack2(unsigned long long v, float& lo, float& hi) {
    unsigned int a, b;
    asm("mov.b64 {%0, %1}, %2;" : "=r"(a), "=r"(b) : "l"(v));
    lo = __uint_as_float(a); hi = __uint_as_float(b);
}

// ---- cp.async helpers -----------------------------------------------------
__device__ __forceinline__ uint32_t smem_u32(const void* p) {
    uint32_t a;
    asm("{ .reg .u64 t; cvta.to.shared.u64 t, %1; cvt.u32.u64 %0, t; }"
        : "=r"(a) : "l"(p));
    return a;
}
__device__ __forceinline__ void cp16(uint32_t dst, const void* src) {
    asm volatile("cp.async.cg.shared.global [%0], [%1], 16;"
                 :: "r"(dst), "l"(src));
}
__device__ __forceinline__ void cp4(uint32_t dst, const void* src) {
    asm volatile("cp.async.ca.shared.global [%0], [%1], 4;"
                 :: "r"(dst), "l"(src));
}
__device__ __forceinline__ void cp_commit() {
    asm volatile("cp.async.commit_group;");
}
template <int N>
__device__ __forceinline__ void cp_wait() {
    asm volatile("cp.async.wait_group %0;" :: "n"(N));
}

// ---- per-thread ZOH weights ----------------------------------------------
__device__ __forceinline__ float2 zoh_L(float ar, float ai, float d) {
    float er = expf(ar * d);
    return make_float2(er * cosf(ai * d), er * sinf(ai * d));
}

// ---------------------------------------------------------------------------
// prep: g_Bw[k][h] = w[h] * (bre[h][k] + i*bim[h][k]); w = (exp(lam d)-1)/lam
// ---------------------------------------------------------------------------
__global__ void prep_kernel(const float* __restrict__ bre,
                            const float* __restrict__ bim,
                            const float* __restrict__ lre,
                            const float* __restrict__ lim,
                            const float* __restrict__ delta) {
    if (!bre || !bim || !lre || !lim) return;
    int idx = blockIdx.x * 256 + threadIdx.x;   // 0 .. 131071
    int k = idx >> 7, h = idx & 127;
    float d  = delta ? delta[0] : 0.01f;
    float ar = lre[h], ai = lim[h];
    float2 L = zoh_L(ar, ai, d);
    float nr = L.x - 1.0f, ni = L.y;
    float inv = 1.0f / (ar * ar + ai * ai);
    float wr = (nr * ar + ni * ai) * inv;
    float wi = (ni * ar - nr * ai) * inv;
    float br = bre[(size_t)h * NIN + k];
    float bi = bim[(size_t)h * NIN + k];
    g_Bw[idx] = make_float2(wr * br - wi * bi, wr * bi + wi * br);
}

// ---------------------------------------------------------------------------
// GEMM: bu[h][m] = sum_k Bw[k][h] * u[m][k]   (complex x real)
// Block: 32h x 64m, 256 threads, micro 4h x 2m (m = tg, tg+32).
// Double-buffered cp.async. Grid: (MM/64 = 32, HH/32 = 4) = 128 blocks
// -> exactly <= 1 block/SM, single wave.
// ---------------------------------------------------------------------------
__global__ void __launch_bounds__(256, 1)
gemm_kernel(const float* __restrict__ u) {
    if (!u) return;

    __shared__ __align__(16) float2 sB[2][KC][32];   // [buf][k][h]  16 KB
    __shared__ float sU[2][64][KC + 1];              // [buf][m][k]  16.5 KB

    int h0  = blockIdx.y * 32;
    int m0  = blockIdx.x * 64;
    int tid = threadIdx.x;            // 0..255
    int hg  = tid >> 5;               // 0..7  -> h_local = hg*4
    int tg  = tid & 31;               // 0..31 -> m_local = tg, tg+32

    uint32_t sB_base = smem_u32(&sB[0][0][0]);
    uint32_t sU_base = smem_u32(&sU[0][0][0]);

    auto issue_chunk = [&](int c, int buf) {
        // B: 32k x 32h float2 = 512 x 16B segs -> 2 per thread
        const float2* gb = g_Bw + (size_t)(c * KC) * HH + h0;
        #pragma unroll
        for (int i = 0; i < 2; i++) {
            int idx = i * 256 + tid;
            int k = idx >> 4, s = idx & 15;
            cp16(sB_base + (uint32_t)((buf * KC + k) * 32 + s * 2) * 8,
                 gb + (size_t)k * HH + s * 2);
        }
        // U: 64m x 32k floats = 2048 x 4B -> 8 per thread (pad 33 keeps
        // LDS reads conflict-free; cp4 tolerates 4B alignment)
        const float* gu = u + (size_t)m0 * NIN + c * KC;
        #pragma unroll
        for (int i = 0; i < 8; i++) {
            int idx = i * 256 + tid;
            int m = idx >> 5, k = idx & 31;
            cp4(sU_base + (uint32_t)((buf * 64 + m) * (KC + 1) + k) * 4,
                gu + (size_t)m * NIN + k);
        }
        cp_commit();
    };

    unsigned long long acc[4][2];
    #pragma unroll
    for (int i = 0; i < 4; i++) { acc[i][0] = 0ull; acc[i][1] = 0ull; }

    issue_chunk(0, 0);

    for (int c = 0; c < NKC; c++) {
        int buf = c & 1;
        if (c + 1 < NKC) { issue_chunk(c + 1, buf ^ 1); cp_wait<1>(); }
        else             { cp_wait<0>(); }
        __syncthreads();

        #pragma unroll 8
        for (int k = 0; k < KC; k++) {
            ulonglong2 B01 = *reinterpret_cast<const ulonglong2*>(&sB[buf][k][hg * 4]);
            ulonglong2 B23 = *reinterpret_cast<const ulonglong2*>(&sB[buf][k][hg * 4 + 2]);
            float u0 = sU[buf][tg     ][k];
            float u1 = sU[buf][tg + 32][k];
            unsigned long long up0 = pack2(u0, u0);
            unsigned long long up1 = pack2(u1, u1);
            acc[0][0] = fma2(B01.x, up0, acc[0][0]);
            acc[0][1] = fma2(B01.x, up1, acc[0][1]);
            acc[1][0] = fma2(B01.y, up0, acc[1][0]);
            acc[1][1] = fma2(B01.y, up1, acc[1][1]);
            acc[2][0] = fma2(B23.x, up0, acc[2][0]);
            acc[2][1] = fma2(B23.x, up1, acc[2][1]);
            acc[3][0] = fma2(B23.y, up0, acc[3][0]);
            acc[3][1] = fma2(B23.y, up1, acc[3][1]);
        }
        __syncthreads();
    }

    #pragma unroll
    for (int hh = 0; hh < 4; hh++) {
        int h = h0 + hg * 4 + hh;
        #pragma unroll
        for (int mi = 0; mi < 2; mi++) {
            int m = m0 + tg + mi * 32;
            int b = m >> 10, t = m & 1023;
            float gr, gi;
            unpack2(acc[hh][mi], gr, gi);
            g_bu[((size_t)b * HH + h) * TT + t] = make_float2(gr, gi);
        }
    }
}

// ---------------------------------------------------------------------------
// Partial kernel: A_c = local scan of chunk c from zero state.
// Grid (256 bh, 7 chunks), 128 threads (h2).
// ---------------------------------------------------------------------------
__global__ void partial_kernel(const float* __restrict__ lre,
                               const float* __restrict__ lim,
                               const float* __restrict__ delta) {
    __shared__ float2 sbu[CH_T];
    int bh = blockIdx.x;
    int ch = blockIdx.y;      // 0..6
    int h2 = threadIdx.x;

    sbu[h2] = g_bu[(size_t)bh * TT + ch * CH_T + h2];
    __syncthreads();

    float d  = delta ? delta[0] : 0.01f;
    float2 L = zoh_L(lre[h2], lim[h2], d);

    float xr = 0.f, xi = 0.f;
    #pragma unroll 4
    for (int t = 0; t < CH_T; t++) {
        float2 c = sbu[t];
        float nr = fmaf(L.x, xr, fmaf(-L.y, xi, c.x));
        float ni = fmaf(L.x, xi, fmaf( L.y, xr, c.y));
        xr = nr; xi = ni;
    }
    g_carry[bh][ch][h2] = make_float2(xr, xi);   // partial A_c
}

// ---------------------------------------------------------------------------
// Combine kernel: carry[c] = A[c] + L^CH_T * carry[c-1]  (in place).
// Grid 256 blocks, 128 threads. L^128 via 7 squarings.
// ---------------------------------------------------------------------------
__global__ void combine_kernel(const float* __restrict__ lre,
                               const float* __restrict__ lim,
                               const float* __restrict__ delta) {
    int bh = blockIdx.x;
    int h2 = threadIdx.x;

    float d  = delta ? delta[0] : 0.01f;
    float2 L = zoh_L(lre[h2], lim[h2], d);
    float pr = L.x, pi = L.y;
    #pragma unroll
    for (int i = 0; i < 7; i++) {        // L^(2^7) = L^128
        float nr = pr * pr - pi * pi;
        float ni = 2.f * pr * pi;
        pr = nr; pi = ni;
    }

    float cr = 0.f, ci = 0.f;
    #pragma unroll
    for (int c = 0; c < NCH - 1; c++) {
        float2 A = g_carry[bh][c][h2];
        float nr = fmaf(pr, cr, fmaf(-pi, ci, A.x));
        float ni = fmaf(pr, ci, fmaf( pi, cr, A.y));
        cr = nr; ci = ni;
        g_carry[bh][c][h2] = make_float2(cr, ci);
    }
}

// ---------------------------------------------------------------------------
// Chunk kernel: grid (256 bh, 8 chunks), 128 threads (h2). Starts from the
// combined carry. Writes real (cmode=0) or interleaved complex (cmode=1).
// ---------------------------------------------------------------------------
__global__ void chunk_kernel(float* __restrict__ out,
                             const float* __restrict__ lre,
                             const float* __restrict__ lim,
                             const float* __restrict__ delta,
                             int cmode, size_t lim_floats) {
    __shared__ float2 sbu[CH_T];

    int bh    = blockIdx.x;
    int chunk = blockIdx.y;
    int h2    = threadIdx.x;
    int t0    = chunk * CH_T;

    sbu[h2] = g_bu[(size_t)bh * TT + t0 + h2];
    __syncthreads();

    float d  = delta ? delta[0] : 0.01f;
    float2 L = zoh_L(lre[h2], lim[h2], d);

    float xr = 0.f, xi = 0.f;
    if (chunk > 0) {
        float2 cs = g_carry[bh][chunk - 1][h2];
        xr = cs.x; xi = cs.y;
    }

    int b = bh >> 7, h1 = bh & 127;
    size_t off = ((size_t)(t0 * BB + b) * HH + h1) * HH + h2;  // complex index
    const size_t stride = (size_t)BB * HH * HH;

    if (cmode) {
        #pragma unroll 4
        for (int t = 0; t < CH_T; t++) {
            float2 c = sbu[t];
            float nr = fmaf(L.x, xr, fmaf(-L.y, xi, c.x));
            float ni = fmaf(L.x, xi, fmaf( L.y, xr, c.y));
            xr = nr; xi = ni;
            if (off * 2 + 1 < lim_floats)
                reinterpret_cast<float2*>(out)[off] = make_float2(xr, xi);
            off += stride;
        }
    } else {
        #pragma unroll 4
        for (int t = 0; t < CH_T; t++) {
            float2 c = sbu[t];
            float nr = fmaf(L.x, xr, fmaf(-L.y, xi, c.x));
            float ni = fmaf(L.x, xi, fmaf( L.y, xr, c.y));
            xr = nr; xi = ni;
            if (off < lim_floats) out[off] = xr;
            off += stride;
        }
    }
}

// ---------------------------------------------------------------------------
// Host: robust binding (proven) + output-mode decision table.
// ---------------------------------------------------------------------------
extern "C" void kernel_launch(void* const* d_in, const int* in_sizes, int n_in,
                              void* d_out, int out_size) {
    int div = 0;
    for (int i = 0; i < n_in && !div; i++) {
        if (in_sizes[i] == U_ELEMS)     div = 1;
        if (in_sizes[i] == U_ELEMS * 4) div = 4;
    }
    if (!div) div = 1;

    const float* u = nullptr;
    const float* delta = nullptr;
    const float* lam[2]  = {nullptr, nullptr};
    const float* bmat[2] = {nullptr, nullptr};
    int nl = 0, nb = 0, u_idx = -1;

    for (int i = 0; i < n_in; i++) {
        long long s = (long long)in_sizes[i] / div;
        const float* p = (const float*)d_in[i];
        if (s == U_ELEMS)        { u = p; u_idx = i; }
        else if (s == 1)           delta = p;
        else if (s == LAM_ELEMS) { if (nl < 2) lam[nl++] = p; }
        else if (s == B_ELEMS)   { if (nb < 2) bmat[nb++] = p; }
    }

    if ((!u || nl < 2 || nb < 2) && n_in >= 6) {   // positional fallback
        u       = (const float*)d_in[0];
        delta   = (const float*)d_in[1];
        lam[0]  = (const float*)d_in[2];
        lam[1]  = (const float*)d_in[3];
        bmat[0] = (const float*)d_in[4];
        bmat[1] = (const float*)d_in[5];
        u_idx = 0; nl = nb = 2;
    }

    bool re_first = (u_idx == 0);
    const float* lre = re_first ? lam[0]  : lam[1];
    const float* lim = re_first ? lam[1]  : lam[0];
    const float* bre = re_first ? bmat[0] : bmat[1];
    const float* bim = re_first ? bmat[1] : bmat[0];

    const long long full_c = (long long)TT * BB * HH * HH;   // 33,554,432
    int cmode; size_t lim_floats;
    long long os = out_size;
    if (os == full_c)          { cmode = 0; lim_floats = (size_t)full_c; }
    else if (os == 2 * full_c) { cmode = 1; lim_floats = (size_t)(2 * full_c); }
    else if (os == 8 * full_c) { cmode = 1; lim_floats = (size_t)(2 * full_c); }
    else if (os == 4 * full_c) { cmode = 0; lim_floats = (size_t)full_c; }
    else { cmode = 0;
           lim_floats = (size_t)(os < full_c ? (os > 0 ? os : 0) : full_c); }

    prep_kernel<<<B_ELEMS / 256, 256>>>(bre, bim, lre, lim, delta);
    gemm_kernel<<<dim3(MM / 64, HH / 32), 256>>>(u);
    partial_kernel<<<dim3(BB * HH, NCH - 1), 128>>>(lre, lim, delta);
    combine_kernel<<<BB * HH, 128>>>(lre, lim, delta);
    chunk_kernel<<<dim3(BB * HH, NCH), 128>>>((float*)d_out, lre, lim, delta,
                                              cmode, lim_floats);
}

// round 9
// speedup vs baseline: 1.6670x; 1.2955x over previous
#include <cuda_runtime.h>
#include <cuda_bf16.h>
#include <cstdint>

#define TT   1024
#define BB   2
#define HH   128
#define NIN  1024
#define MM   (BB * TT)          // 2048
#define NN   (2 * HH)           // 256 output cols (re,im interleaved)
#define CH_T 128
#define NCH  (TT / CH_T)        // 8

#define U_ELEMS   (BB * TT * NIN)
#define LAM_ELEMS (HH)
#define B_ELEMS   (HH * NIN)

// GEMM tiling (mma.sync path; tcgen05 unavailable: harness targets sm_103)
#define MT 64
#define NT 64
#define KTILE 64                       // bf16 per smem chunk row
#define NTERMS 3                       // uhi*Bhi + uhi*Blo + ulo*Bhi
#define NCHUNK (NTERMS * NIN / KTILE)  // 48
#define TILE_BYTES (64 * 128)          // 8192 (64 rows x 128B)

// device scratch
__device__ __nv_bfloat16 g_uhi[MM * NIN];
__device__ __nv_bfloat16 g_ulo[MM * NIN];
__device__ __nv_bfloat16 g_Bhi[NN * NIN];
__device__ __nv_bfloat16 g_Blo[NN * NIN];
__device__ float2 g_bu[MM * HH];                // bu[(b*HH+h)*TT + t]
__device__ float2 g_part[BB * HH][NCH - 1][HH]; // per-chunk partial states

// ---- PTX helpers ----------------------------------------------------------
__device__ __forceinline__ uint32_t smem_u32(const void* p) {
    uint32_t a;
    asm("{ .reg .u64 t; cvta.to.shared.u64 t, %1; cvt.u32.u64 %0, t; }"
        : "=r"(a) : "l"(p));
    return a;
}
__device__ __forceinline__ uint32_t sw128(uint32_t off) {
    return off ^ ((off >> 3) & 0x70);
}
__device__ __forceinline__ void cp16(uint32_t dst, const void* src) {
    asm volatile("cp.async.cg.shared.global [%0], [%1], 16;"
                 :: "r"(dst), "l"(src));
}
__device__ __forceinline__ void cp_commit() {
    asm volatile("cp.async.commit_group;");
}
template <int N> __device__ __forceinline__ void cp_wait() {
    asm volatile("cp.async.wait_group %0;" :: "n"(N));
}
__device__ __forceinline__ void ldsm4(uint32_t& r0, uint32_t& r1,
                                      uint32_t& r2, uint32_t& r3,
                                      uint32_t addr) {
    asm volatile("ldmatrix.sync.aligned.m8n8.x4.shared.b16 {%0,%1,%2,%3}, [%4];"
                 : "=r"(r0), "=r"(r1), "=r"(r2), "=r"(r3) : "r"(addr));
}
__device__ __forceinline__ void mma_bf16(float& c0, float& c1, float& c2,
                                         float& c3, uint32_t a0, uint32_t a1,
                                         uint32_t a2, uint32_t a3,
                                         uint32_t b0, uint32_t b1) {
    asm volatile(
        "mma.sync.aligned.m16n8k16.row.col.f32.bf16.bf16.f32 "
        "{%0,%1,%2,%3}, {%4,%5,%6,%7}, {%8,%9}, {%0,%1,%2,%3};"
        : "+f"(c0), "+f"(c1), "+f"(c2), "+f"(c3)
        : "r"(a0), "r"(a1), "r"(a2), "r"(a3), "r"(b0), "r"(b1));
}
__device__ __forceinline__ float2 zoh_L(float ar, float ai, float d) {
    float er = expf(ar * d);
    return make_float2(er * cosf(ai * d), er * sinf(ai * d));
}

// ---------------------------------------------------------------------------
// prep: blocks [0,2048): split u into bf16 hi/lo.
//       blocks [2048,2304): Bw = w*(bre+i bim); bf16 hi/lo, layout [n][k],
//       n = 2h + comp (0=re,1=im).
// ---------------------------------------------------------------------------
__global__ void prep_kernel(const float* __restrict__ u,
                            const float* __restrict__ bre,
                            const float* __restrict__ bim,
                            const float* __restrict__ lre,
                            const float* __restrict__ lim,
                            const float* __restrict__ delta) {
    int blk = blockIdx.x;
    if (blk < 2048) {
        if (!u) return;
        int e0 = blk * 1024 + threadIdx.x;
        #pragma unroll
        for (int i = 0; i < 4; i++) {
            int e = e0 + i * 256;
            float f = u[e];
            __nv_bfloat16 hi = __float2bfloat16(f);
            g_uhi[e] = hi;
            g_ulo[e] = __float2bfloat16(f - __bfloat162float(hi));
        }
    } else {
        if (!bre || !bim || !lre || !lim) return;
        float d = delta ? delta[0] : 0.01f;
        int e0 = (blk - 2048) * 1024 + threadIdx.x;
        #pragma unroll
        for (int i = 0; i < 4; i++) {
            int e = e0 + i * 256;
            int n = e >> 10, k = e & 1023;
            int h = n >> 1;
            float ar = lre[h], ai = lim[h];
            float2 L = zoh_L(ar, ai, d);
            float nr = L.x - 1.0f, ni = L.y;
            float inv = 1.0f / (ar * ar + ai * ai);
            float wr = (nr * ar + ni * ai) * inv;
            float wi = (ni * ar - nr * ai) * inv;
            float br = bre[(size_t)h * NIN + k];
            float bi = bim[(size_t)h * NIN + k];
            float val = (n & 1) ? (wr * bi + wi * br)    // imag
                                : (wr * br - wi * bi);   // real
            __nv_bfloat16 hi = __float2bfloat16(val);
            g_Bhi[e] = hi;
            g_Blo[e] = __float2bfloat16(val - __bfloat162float(hi));
        }
    }
}

// ---------------------------------------------------------------------------
// GEMM via mma.sync bf16: D[m][n] = sum of 3 split terms of A[m][k]*B[n][k].
// CTA 64m x 64n, 256 threads (8 warps, warp tile 32m x 16n).
// 48 K-chunks of 64, double-buffered cp.async, SW128 swizzle for ldmatrix.
// Grid (MM/64 = 32, NN/64 = 4) = 128 CTAs, single wave.
// ---------------------------------------------------------------------------
__global__ void __launch_bounds__(256, 1)
gemm_kernel() {
    __shared__ __align__(1024) uint8_t smem[4 * TILE_BYTES];  // A0 A1 B0 B1

    int tid = threadIdx.x, wid = tid >> 5, lane = tid & 31;
    int m0 = blockIdx.x * MT;
    int n0 = blockIdx.y * NT;
    int warp_m = wid & 1;        // 0..1 -> m offset 0/32
    int warp_n = wid >> 1;       // 0..3 -> n offset 0/16/32/48

    uint32_t sA[2] = { smem_u32(smem),              smem_u32(smem) + TILE_BYTES };
    uint32_t sB[2] = { smem_u32(smem) + 2 * TILE_BYTES,
                       smem_u32(smem) + 3 * TILE_BYTES };

    // Precompute per-thread ldmatrix offsets (within a tile, swizzled).
    // A (x4, 16x16): lanes 0-15 rows 0-15 @ kbyte 0; 16-31 same rows @ +16B.
    uint32_t offA[2][4];
    {
        uint32_t row = (uint32_t)(warp_m * 32 + (lane & 15));
        uint32_t kb  = (uint32_t)((lane >> 4) * 16);
        #pragma unroll
        for (int mt = 0; mt < 2; mt++)
            #pragma unroll
            for (int s = 0; s < 4; s++)
                offA[mt][s] = sw128((row + mt * 16) * 128 + s * 32 + kb);
    }
    // B (x4, 16n x 16k): g=lane/8: (n0-7,k0),(n0-7,k+16B),(n8-15,k0),(n8-15,k+16B)
    uint32_t offB[4];
    {
        uint32_t row = (uint32_t)(warp_n * 16 + (lane & 7) + ((lane >> 4) << 3));
        uint32_t kb  = (uint32_t)(((lane >> 3) & 1) * 16);
        #pragma unroll
        for (int s = 0; s < 4; s++)
            offB[s] = sw128(row * 128 + s * 32 + kb);
    }

    auto load_chunk = [&](int c, int buf) {
        int term = c >> 4;                // 0,1: u_hi ; 2: u_lo
        int k0   = (c & 15) * KTILE;
        const __nv_bfloat16* ga = (term == 2 ? g_ulo : g_uhi)
                                  + (size_t)m0 * NIN + k0;
        const __nv_bfloat16* gb = (term == 1 ? g_Blo : g_Bhi)
                                  + (size_t)n0 * NIN + k0;
        #pragma unroll
        for (int i = 0; i < 2; i++) {          // A: 64 rows x 8 x 16B segs
            int idx = i * 256 + tid;
            int r = idx >> 3, s = idx & 7;
            cp16(sA[buf] + sw128((uint32_t)(r * 128 + s * 16)),
                 ga + (size_t)r * NIN + s * 8);
        }
        #pragma unroll
        for (int i = 0; i < 2; i++) {          // B: 64 rows x 8 x 16B segs
            int idx = i * 256 + tid;
            int r = idx >> 3, s = idx & 7;
            cp16(sB[buf] + sw128((uint32_t)(r * 128 + s * 16)),
                 gb + (size_t)r * NIN + s * 8);
        }
        cp_commit();
    };

    float acc[2][2][4];
    #pragma unroll
    for (int i = 0; i < 2; i++)
        #pragma unroll
        for (int j = 0; j < 2; j++)
            #pragma unroll
            for (int q = 0; q < 4; q++) acc[i][j][q] = 0.f;

    load_chunk(0, 0);

    for (int c = 0; c < NCHUNK; c++) {
        int buf = c & 1;
        if (c + 1 < NCHUNK) { load_chunk(c + 1, buf ^ 1); cp_wait<1>(); }
        else                { cp_wait<0>(); }
        __syncthreads();

        #pragma unroll
        for (int s = 0; s < 4; s++) {
            uint32_t a0[4], a1[4], b[4];
            ldsm4(a0[0], a0[1], a0[2], a0[3], sA[buf] + offA[0][s]);
            ldsm4(a1[0], a1[1], a1[2], a1[3], sA[buf] + offA[1][s]);
            ldsm4(b[0],  b[1],  b[2],  b[3],  sB[buf] + offB[s]);
            mma_bf16(acc[0][0][0], acc[0][0][1], acc[0][0][2], acc[0][0][3],
                     a0[0], a0[1], a0[2], a0[3], b[0], b[1]);
            mma_bf16(acc[0][1][0], acc[0][1][1], acc[0][1][2], acc[0][1][3],
                     a0[0], a0[1], a0[2], a0[3], b[2], b[3]);
            mma_bf16(acc[1][0][0], acc[1][0][1], acc[1][0][2], acc[1][0][3],
                     a1[0], a1[1], a1[2], a1[3], b[0], b[1]);
            mma_bf16(acc[1][1][0], acc[1][1][1], acc[1][1][2], acc[1][1][3],
                     a1[0], a1[1], a1[2], a1[3], b[2], b[3]);
        }
        __syncthreads();
    }

    // Epilogue: thread holds (c0,c1) = (re,im) of one h at row lane/4, and
    // (c2,c3) at row lane/4+8. Direct float2 stores.
    int hb = (n0 >> 1) + warp_n * 8;
    #pragma unroll
    for (int mt = 0; mt < 2; mt++) {
        #pragma unroll
        for (int nt = 0; nt < 2; nt++) {
            int h = hb + nt * 4 + (lane & 3);
            int m1 = m0 + warp_m * 32 + mt * 16 + (lane >> 2);
            int b1 = m1 >> 10, t1 = m1 & 1023;
            g_bu[((size_t)b1 * HH + h) * TT + t1] =
                make_float2(acc[mt][nt][0], acc[mt][nt][1]);
            int m2 = m1 + 8;
            int b2 = m2 >> 10, t2 = m2 & 1023;
            g_bu[((size_t)b2 * HH + h) * TT + t2] =
                make_float2(acc[mt][nt][2], acc[mt][nt][3]);
        }
    }
}

// ---------------------------------------------------------------------------
// Partial kernel: A_c = local scan of chunk c from zero. Grid (256, 7), 128.
// ---------------------------------------------------------------------------
__global__ void partial_kernel(const float* __restrict__ lre,
                               const float* __restrict__ lim,
                               const float* __restrict__ delta) {
    __shared__ float2 sbu[CH_T];
    int bh = blockIdx.x;
    int ch = blockIdx.y;
    int h2 = threadIdx.x;

    sbu[h2] = g_bu[(size_t)bh * TT + ch * CH_T + h2];
    __syncthreads();

    float d  = delta ? delta[0] : 0.01f;
    float2 L = zoh_L(lre[h2], lim[h2], d);

    float xr = 0.f, xi = 0.f;
    #pragma unroll 4
    for (int t = 0; t < CH_T; t++) {
        float2 c = sbu[t];
        float nr = fmaf(L.x, xr, fmaf(-L.y, xi, c.x));
        float ni = fmaf(L.x, xi, fmaf( L.y, xr, c.y));
        xr = nr; xi = ni;
    }
    g_part[bh][ch][h2] = make_float2(xr, xi);
}

// ---------------------------------------------------------------------------
// Chunk kernel: combine partials inline, scan + write chunk.
// Grid (256, 8), 128 threads (thread = h2).
// ---------------------------------------------------------------------------
__global__ void chunk_kernel(float* __restrict__ out,
                             const float* __restrict__ lre,
                             const float* __restrict__ lim,
                             const float* __restrict__ delta,
                             int cmode, size_t lim_floats) {
    __shared__ float2 sbu[CH_T];

    int bh    = blockIdx.x;
    int chunk = blockIdx.y;
    int h2    = threadIdx.x;
    int t0    = chunk * CH_T;

    sbu[h2] = g_bu[(size_t)bh * TT + t0 + h2];
    __syncthreads();

    float d  = delta ? delta[0] : 0.01f;
    float2 L = zoh_L(lre[h2], lim[h2], d);

    float xr = 0.f, xi = 0.f;
    if (chunk > 0) {
        float pr = L.x, pi = L.y;
        #pragma unroll
        for (int i = 0; i < 7; i++) {      // P = L^128
            float nr = pr * pr - pi * pi;
            float ni = 2.f * pr * pi;
            pr = nr; pi = ni;
        }
        for (int j = 0; j < chunk; j++) {  // carry_{chunk-1}
            float2 A = g_part[bh][j][h2];
            float nr = fmaf(pr, xr, fmaf(-pi, xi, A.x));
            float ni = fmaf(pr, xi, fmaf( pi, xr, A.y));
            xr = nr; xi = ni;
        }
    }

    int b = bh >> 7, h1 = bh & 127;
    size_t off = ((size_t)(t0 * BB + b) * HH + h1) * HH + h2;
    const size_t stride = (size_t)BB * HH * HH;

    if (cmode) {
        #pragma unroll 4
        for (int t = 0; t < CH_T; t++) {
            float2 c = sbu[t];
            float nr = fmaf(L.x, xr, fmaf(-L.y, xi, c.x));
            float ni = fmaf(L.x, xi, fmaf( L.y, xr, c.y));
            xr = nr; xi = ni;
            if (off * 2 + 1 < lim_floats)
                reinterpret_cast<float2*>(out)[off] = make_float2(xr, xi);
            off += stride;
        }
    } else {
        #pragma unroll 4
        for (int t = 0; t < CH_T; t++) {
            float2 c = sbu[t];
            float nr = fmaf(L.x, xr, fmaf(-L.y, xi, c.x));
            float ni = fmaf(L.x, xi, fmaf( L.y, xr, c.y));
            xr = nr; xi = ni;
            if (off < lim_floats) out[off] = xr;
            off += stride;
        }
    }
}

// ---------------------------------------------------------------------------
// Host: robust binding (proven) + output-mode decision table.
// ---------------------------------------------------------------------------
extern "C" void kernel_launch(void* const* d_in, const int* in_sizes, int n_in,
                              void* d_out, int out_size) {
    int div = 0;
    for (int i = 0; i < n_in && !div; i++) {
        if (in_sizes[i] == U_ELEMS)     div = 1;
        if (in_sizes[i] == U_ELEMS * 4) div = 4;
    }
    if (!div) div = 1;

    const float* u = nullptr;
    const float* delta = nullptr;
    const float* lam[2]  = {nullptr, nullptr};
    const float* bmat[2] = {nullptr, nullptr};
    int nl = 0, nb = 0, u_idx = -1;

    for (int i = 0; i < n_in; i++) {
        long long s = (long long)in_sizes[i] / div;
        const float* p = (const float*)d_in[i];
        if (s == U_ELEMS)        { u = p; u_idx = i; }
        else if (s == 1)           delta = p;
        else if (s == LAM_ELEMS) { if (nl < 2) lam[nl++] = p; }
        else if (s == B_ELEMS)   { if (nb < 2) bmat[nb++] = p; }
    }

    if ((!u || nl < 2 || nb < 2) && n_in >= 6) {
        u       = (const float*)d_in[0];
        delta   = (const float*)d_in[1];
        lam[0]  = (const float*)d_in[2];
        lam[1]  = (const float*)d_in[3];
        bmat[0] = (const float*)d_in[4];
        bmat[1] = (const float*)d_in[5];
        u_idx = 0; nl = nb = 2;
    }

    bool re_first = (u_idx == 0);
    const float* lre = re_first ? lam[0]  : lam[1];
    const float* lim = re_first ? lam[1]  : lam[0];
    const float* bre = re_first ? bmat[0] : bmat[1];
    const float* bim = re_first ? bmat[1] : bmat[0];

    const long long full_c = (long long)TT * BB * HH * HH;   // 33,554,432
    int cmode; size_t lim_floats;
    long long os = out_size;
    if (os == full_c)          { cmode = 0; lim_floats = (size_t)full_c; }
    else if (os == 2 * full_c) { cmode = 1; lim_floats = (size_t)(2 * full_c); }
    else if (os == 8 * full_c) { cmode = 1; lim_floats = (size_t)(2 * full_c); }
    else if (os == 4 * full_c) { cmode = 0; lim_floats = (size_t)full_c; }
    else { cmode = 0;
           lim_floats = (size_t)(os < full_c ? (os > 0 ? os : 0) : full_c); }

    prep_kernel<<<2304, 256>>>(u, bre, bim, lre, lim, delta);
    gemm_kernel<<<dim3(MM / MT, NN / NT), 256>>>();
    partial_kernel<<<dim3(BB * HH, NCH - 1), 128>>>(lre, lim, delta);
    chunk_kernel<<<dim3(BB * HH, NCH), 128>>>((float*)d_out, lre, lim, delta,
                                              cmode, lim_floats);
}